// round 1
// baseline (speedup 1.0000x reference)
#include <cuda_runtime.h>
#include <math.h>

// ---------------- problem constants ----------------
#define N0v 100000
#define N1v 20000
#define N2v 4000
#define RRv 3
#define E0v 160000
#define E1v 64000
#define HIDv 128

// ---------------- device scratch (allocation-free rule: __device__ globals) ----------------
__device__ float g_feat0[(size_t)N0v * 256];     // 102.4 MB  concat(embed, tss, rs) block0 src feats
__device__ float g_feat1[(size_t)N1v * 256];     // 20.5 MB   layer-1 output concat feats
__device__ float g_msg[(size_t)N1v * 768];       // 61.4 MB   [max, mean, sum] per dst (reused across rel/layer)
__device__ float g_inp[(size_t)N1v * 256];       // 20.5 MB   relu(concat(fc2 out, fc1 out))
__device__ float g_z[(size_t)RRv * N1v * HIDv];  // 30.7 MB   per-relation conv outputs
__device__ float g_t[(size_t)RRv * N1v * HIDv];  // 30.7 MB   tanh buffer for attention
__device__ float g_h2[(size_t)N2v * HIDv];       // 2 MB
__device__ int   g_cnt[N1v];
__device__ int   g_off[N1v + 1];
__device__ int   g_cur[N1v];
__device__ int   g_sorted[E0v];
__device__ float g_partial[8192];
__device__ float g_beta[4];

// ---------------- SGEMM, N fixed at 128: C[M,128] = act(A[M,K] @ B[K,128] + bias) ----------------
// ACT: 0=none, 1=relu, 2=tanh
template <int ACT>
__global__ void __launch_bounds__(256) sgemm128(
    const float* __restrict__ A, const float* __restrict__ B,
    const float* __restrict__ bias, float* __restrict__ C,
    int M, int K, int lda, int ldc)
{
    __shared__ float As[16][128];
    __shared__ float Bs[16][128];
    const int tid = threadIdx.x;
    const int m0 = blockIdx.x * 128;
    const int tx = tid & 15;    // col group
    const int ty = tid >> 4;    // row group

    float acc[8][8];
#pragma unroll
    for (int i = 0; i < 8; i++)
#pragma unroll
        for (int j = 0; j < 8; j++) acc[i][j] = 0.f;

    for (int k0 = 0; k0 < K; k0 += 16) {
        // load A tile 128x16 (transposed into As[k][m]); guard rows >= M with zeros
#pragma unroll
        for (int l = 0; l < 2; l++) {
            int f = tid + l * 256;          // float4 id 0..511
            int r = f >> 2, c4 = f & 3;     // row 0..127, col4 0..3
            int gr = m0 + r;
            float4 v = make_float4(0.f, 0.f, 0.f, 0.f);
            if (gr < M) v = *reinterpret_cast<const float4*>(&A[(size_t)gr * lda + k0 + c4 * 4]);
            As[c4 * 4 + 0][r] = v.x;
            As[c4 * 4 + 1][r] = v.y;
            As[c4 * 4 + 2][r] = v.z;
            As[c4 * 4 + 3][r] = v.w;
        }
        // load B tile 16x128 (row-major, ldb = 128)
#pragma unroll
        for (int l = 0; l < 2; l++) {
            int f = tid + l * 256;
            int r = f >> 5, c4 = f & 31;
            *reinterpret_cast<float4*>(&Bs[r][c4 * 4]) =
                *reinterpret_cast<const float4*>(&B[(size_t)(k0 + r) * 128 + c4 * 4]);
        }
        __syncthreads();
#pragma unroll
        for (int k = 0; k < 16; k++) {
            float4 a0 = *reinterpret_cast<const float4*>(&As[k][ty * 8]);
            float4 a1 = *reinterpret_cast<const float4*>(&As[k][ty * 8 + 4]);
            float4 b0 = *reinterpret_cast<const float4*>(&Bs[k][tx * 8]);
            float4 b1 = *reinterpret_cast<const float4*>(&Bs[k][tx * 8 + 4]);
            float ra[8] = {a0.x, a0.y, a0.z, a0.w, a1.x, a1.y, a1.z, a1.w};
            float rb[8] = {b0.x, b0.y, b0.z, b0.w, b1.x, b1.y, b1.z, b1.w};
#pragma unroll
            for (int i = 0; i < 8; i++)
#pragma unroll
                for (int j = 0; j < 8; j++) acc[i][j] += ra[i] * rb[j];
        }
        __syncthreads();
    }

#pragma unroll
    for (int i = 0; i < 8; i++) {
        int gr = m0 + ty * 8 + i;
        if (gr >= M) continue;
#pragma unroll
        for (int j = 0; j < 8; j += 4) {
            int gc = tx * 8 + j;
            float4 v;
            v.x = acc[i][j + 0] + bias[gc + 0];
            v.y = acc[i][j + 1] + bias[gc + 1];
            v.z = acc[i][j + 2] + bias[gc + 2];
            v.w = acc[i][j + 3] + bias[gc + 3];
            if (ACT == 1) {
                v.x = fmaxf(v.x, 0.f); v.y = fmaxf(v.y, 0.f);
                v.z = fmaxf(v.z, 0.f); v.w = fmaxf(v.w, 0.f);
            } else if (ACT == 2) {
                v.x = tanhf(v.x); v.y = tanhf(v.y); v.z = tanhf(v.z); v.w = tanhf(v.w);
            }
            *reinterpret_cast<float4*>(&C[(size_t)gr * ldc + gc]) = v;
        }
    }
}

// ---------------- gather tss/rs into feat cols [128:256) ----------------
__global__ void gather_emb(const float* __restrict__ tss, const float* __restrict__ rs,
                           const int* __restrict__ nid, float* __restrict__ feat, int n)
{
    int i = blockIdx.x * blockDim.x + threadIdx.x;
    int row = i >> 7, c = i & 127;
    if (row < n) {
        int g = nid[row];
        feat[(size_t)row * 256 + 128 + c] = (c < 64) ? tss[(size_t)g * 64 + c]
                                                     : rs[(size_t)g * 64 + (c - 64)];
    }
}

// ---------------- CSR build ----------------
__global__ void hist_k(const int* __restrict__ dst, int* __restrict__ cnt, int E)
{
    int e = blockIdx.x * blockDim.x + threadIdx.x;
    if (e < E) atomicAdd(&cnt[dst[e]], 1);
}

__global__ void scan_k(const int* __restrict__ cnt, int* __restrict__ off,
                       int* __restrict__ cur, int n)
{
    __shared__ int sh[1024];
    __shared__ int carry;
    if (threadIdx.x == 0) carry = 0;
    __syncthreads();
    for (int base = 0; base < n; base += 1024) {
        int i = base + threadIdx.x;
        int v = (i < n) ? cnt[i] : 0;
        sh[threadIdx.x] = v;
        __syncthreads();
        for (int d = 1; d < 1024; d <<= 1) {
            int t = (threadIdx.x >= d) ? sh[threadIdx.x - d] : 0;
            __syncthreads();
            sh[threadIdx.x] += t;
            __syncthreads();
        }
        int excl = sh[threadIdx.x] - v + carry;
        if (i < n) { off[i] = excl; cur[i] = excl; }
        __syncthreads();
        if (threadIdx.x == 1023) carry += sh[1023];
        __syncthreads();
    }
    if (threadIdx.x == 0) off[n] = carry;
}

__global__ void scatter_k(const int* __restrict__ src, const int* __restrict__ dst,
                          int* __restrict__ cur, int* __restrict__ sorted, int E)
{
    int e = blockIdx.x * blockDim.x + threadIdx.x;
    if (e < E) {
        int d = dst[e];
        int p = atomicAdd(&cur[d], 1);
        sorted[p] = src[e];
    }
}

// ---------------- aggregation: one block (256 thr) per dst; deterministic via neighbor sort ----------------
__global__ void aggregate_k(const float* __restrict__ feat, const int* __restrict__ off,
                            const int* __restrict__ sorted, float* __restrict__ msg)
{
    __shared__ int idx[1024];
    int d = blockIdx.x;
    int s0 = off[d], s1 = off[d + 1];
    int deg = s1 - s0;
    if (deg > 1024) deg = 1024;  // unreachable for these graphs; OOB guard
    for (int i = threadIdx.x; i < deg; i += blockDim.x) idx[i] = sorted[s0 + i];
    __syncthreads();
    // odd-even transposition sort (deterministic accumulation order)
    for (int p = 0; p < deg; p++) {
        for (int j = (p & 1) + 2 * threadIdx.x; j + 1 < deg; j += 2 * blockDim.x) {
            int a = idx[j], b = idx[j + 1];
            if (a > b) { idx[j] = b; idx[j + 1] = a; }
        }
        __syncthreads();
    }
    int c = threadIdx.x;  // feature column 0..255
    float sum = 0.f, mx = -INFINITY;
    for (int i = 0; i < deg; i++) {
        float v = __ldg(&feat[(size_t)idx[i] * 256 + c]);
        sum += v;
        mx = fmaxf(mx, v);
    }
    float mean = deg ? sum / (float)deg : 0.f;
    if (!deg) mx = 0.f;
    size_t b = (size_t)d * 768;
    msg[b + c] = mx;
    msg[b + 256 + c] = mean;
    msg[b + 512 + c] = sum;
}

// ---------------- attention ----------------
__global__ void attn_dot(const float* __restrict__ t, const float* __restrict__ w2,
                         float* __restrict__ partial, int totalrows)
{
    __shared__ float sh[8];
    int warp = threadIdx.x >> 5, lane = threadIdx.x & 31;
    int row = blockIdx.x * 8 + warp;
    float s = 0.f;
    if (row < totalrows) {
        const float* tr = &t[(size_t)row * 128];
        for (int i = lane; i < 128; i += 32) s += tr[i] * w2[i];
    }
    for (int o = 16; o; o >>= 1) s += __shfl_xor_sync(0xFFFFFFFFu, s, o);
    if (!lane) sh[warp] = s;
    __syncthreads();
    if (threadIdx.x == 0) {
        float tot = 0.f;
        for (int i = 0; i < 8; i++) tot += sh[i];
        partial[blockIdx.x] = tot;
    }
}

__global__ void attn_fin(const float* __restrict__ partial, int bpr, float invN,
                         float* __restrict__ beta)
{
    __shared__ float sh[256];
    __shared__ float w[3];
    for (int r = 0; r < 3; r++) {
        float s = 0.f;
        for (int i = threadIdx.x; i < bpr; i += 256) s += partial[r * bpr + i];
        sh[threadIdx.x] = s;
        __syncthreads();
        for (int o = 128; o; o >>= 1) {
            if (threadIdx.x < o) sh[threadIdx.x] += sh[threadIdx.x + o];
            __syncthreads();
        }
        if (threadIdx.x == 0) w[r] = sh[0] * invN;
        __syncthreads();
    }
    if (threadIdx.x == 0) {
        float m = fmaxf(w[0], fmaxf(w[1], w[2]));
        float e0 = expf(w[0] - m), e1 = expf(w[1] - m), e2 = expf(w[2] - m);
        float inv = 1.f / (e0 + e1 + e2);
        beta[0] = e0 * inv; beta[1] = e1 * inv; beta[2] = e2 * inv;
    }
}

__global__ void combine_k(const float* __restrict__ z, const float* __restrict__ beta,
                          float* __restrict__ outf, int n, int zstride, int ldc, int do_relu)
{
    int i = blockIdx.x * blockDim.x + threadIdx.x;
    int row = i >> 7, c = i & 127;
    if (row < n) {
        size_t o = (size_t)row * 128 + c;
        float v = beta[0] * z[o] + beta[1] * z[o + (size_t)zstride] + beta[2] * z[o + 2 * (size_t)zstride];
        if (do_relu) v = fmaxf(v, 0.f);
        outf[(size_t)row * ldc + c] = v;
    }
}

// ---------------- predictor ----------------
__global__ void pred_k(const float* __restrict__ h, const float* __restrict__ w,
                       const float* __restrict__ b, float* __restrict__ out, int n)
{
    int gwarp = (blockIdx.x * blockDim.x + threadIdx.x) >> 5;
    int lane = threadIdx.x & 31;
    if (gwarp < n) {
        const float* hr = &h[(size_t)gwarp * 128];
        float s = 0.f;
        for (int i = lane; i < 128; i += 32) s += hr[i] * w[i];
        for (int o = 16; o; o >>= 1) s += __shfl_xor_sync(0xFFFFFFFFu, s, o);
        if (!lane) out[gwarp] = 1.f / (1.f + expf(-(s + b[0])));
    }
}

// ---------------- host orchestration ----------------
static inline int cdiv(int a, int b) { return (a + b - 1) / b; }

extern "C" void kernel_launch(void* const* d_in, const int* in_sizes, int n_in,
                              void* d_out, int out_size)
{
    const float* x_user   = (const float*)d_in[0];
    const float* tss      = (const float*)d_in[1];
    const float* rs       = (const float*)d_in[2];
    const int*   src_nid0 = (const int*)d_in[3];
    const int*   src_nid1 = (const int*)d_in[4];
    const int*   e0_src   = (const int*)d_in[5];
    const int*   e0_dst   = (const int*)d_in[6];
    const int*   e1_src   = (const int*)d_in[7];
    const int*   e1_dst   = (const int*)d_in[8];
    const float* embed_w  = (const float*)d_in[9];
    const float* embed_b  = (const float*)d_in[10];
    const float* attn_w1  = (const float*)d_in[23];
    const float* attn_b1  = (const float*)d_in[24];
    const float* attn_w2  = (const float*)d_in[25];
    const float* pred_w   = (const float*)d_in[26];
    const float* pred_b   = (const float*)d_in[27];
    float* out = (float*)d_out;

    float *feat0, *feat1, *msg, *inp, *z, *t, *h2, *partial, *beta;
    int *cnt, *off, *cur, *sorted;
    cudaGetSymbolAddress((void**)&feat0, g_feat0);
    cudaGetSymbolAddress((void**)&feat1, g_feat1);
    cudaGetSymbolAddress((void**)&msg, g_msg);
    cudaGetSymbolAddress((void**)&inp, g_inp);
    cudaGetSymbolAddress((void**)&z, g_z);
    cudaGetSymbolAddress((void**)&t, g_t);
    cudaGetSymbolAddress((void**)&h2, g_h2);
    cudaGetSymbolAddress((void**)&partial, g_partial);
    cudaGetSymbolAddress((void**)&beta, g_beta);
    cudaGetSymbolAddress((void**)&cnt, g_cnt);
    cudaGetSymbolAddress((void**)&off, g_off);
    cudaGetSymbolAddress((void**)&cur, g_cur);
    cudaGetSymbolAddress((void**)&sorted, g_sorted);

    // feat0 = [x_user @ embed_w + b | tss[src_nid0] | rs[src_nid0]]
    sgemm128<0><<<cdiv(N0v, 128), 256>>>(x_user, embed_w, embed_b, feat0, N0v, 128, 128, 256);
    gather_emb<<<cdiv(N0v * 128, 256), 256>>>(tss, rs, src_nid0, feat0, N0v);

    for (int layer = 0; layer < 2; layer++) {
        const int E = layer ? E1v : E0v;
        const int ndst = layer ? N2v : N1v;
        const int* esrc = layer ? e1_src : e0_src;
        const int* edst = layer ? e1_dst : e0_dst;
        const float* srcfeat = layer ? feat1 : feat0;
        const float* fc1w = (const float*)d_in[11 + layer * 6];
        const float* fc1b = (const float*)d_in[12 + layer * 6];
        const float* fc2w = (const float*)d_in[13 + layer * 6];
        const float* fc2b = (const float*)d_in[14 + layer * 6];
        const float* fc3w = (const float*)d_in[15 + layer * 6];
        const float* fc3b = (const float*)d_in[16 + layer * 6];

        for (int r = 0; r < 3; r++) {
            const int* es = esrc + (size_t)r * E;
            const int* ed = edst + (size_t)r * E;
            cudaMemsetAsync(cnt, 0, ndst * sizeof(int));
            hist_k<<<cdiv(E, 256), 256>>>(ed, cnt, E);
            scan_k<<<1, 1024>>>(cnt, off, cur, ndst);
            scatter_k<<<cdiv(E, 256), 256>>>(es, ed, cur, sorted, E);
            aggregate_k<<<ndst, 256>>>(srcfeat, off, sorted, msg);
            // inp[:,0:128]   = relu(msg @ fc2w[r] + b2)
            sgemm128<1><<<cdiv(ndst, 128), 256>>>(msg, fc2w + (size_t)r * 768 * 128,
                                                  fc2b + r * 128, inp, ndst, 768, 768, 256);
            // inp[:,128:256] = relu(dstfeat @ fc1w[r] + b1)
            sgemm128<1><<<cdiv(ndst, 128), 256>>>(srcfeat, fc1w + (size_t)r * 256 * 128,
                                                  fc1b + r * 128, inp + 128, ndst, 256, 256, 256);
            // z[r] = inp @ fc3w[r] + b3
            sgemm128<0><<<cdiv(ndst, 128), 256>>>(inp, fc3w + (size_t)r * 256 * 128,
                                                  fc3b + r * 128, z + (size_t)r * ndst * 128,
                                                  ndst, 256, 256, 128);
        }

        // semantic attention over z [3, ndst, 128]
        int rows = 3 * ndst;
        sgemm128<2><<<cdiv(rows, 128), 256>>>(z, attn_w1, attn_b1, t, rows, 128, 128, 128);
        attn_dot<<<rows / 8, 256>>>(t, attn_w2, partial, rows);
        attn_fin<<<1, 256>>>(partial, ndst / 8, 1.f / (float)ndst, beta);

        if (layer == 0) {
            combine_k<<<cdiv(ndst * 128, 256), 256>>>(z, beta, feat1, ndst, ndst * 128, 256, 1);
            gather_emb<<<cdiv(ndst * 128, 256), 256>>>(tss, rs, src_nid1, feat1, ndst);
        } else {
            combine_k<<<cdiv(ndst * 128, 256), 256>>>(z, beta, h2, ndst, ndst * 128, 128, 0);
        }
    }

    pred_k<<<cdiv(N2v * 32, 256), 256>>>(h2, pred_w, pred_b, out, N2v);
}

// round 2
// speedup vs baseline: 1.5355x; 1.5355x over previous
#include <cuda_runtime.h>
#include <math.h>

// ---------------- problem constants ----------------
#define N0v 100000
#define N1v 20000
#define N2v 4000
#define E0v 160000
#define E1v 64000

// ---------------- device scratch (allocation-free rule: __device__ globals) ----------------
__device__ float g_feat0[(size_t)N0v * 256];      // concat(embed, tss, rs) block0 src feats
__device__ float g_feat1[(size_t)N1v * 256];      // layer-1 output concat feats
__device__ float g_msg[(size_t)3 * N1v * 768];    // [r][dst][max|mean|sum]
__device__ float g_inp[(size_t)3 * N1v * 256];    // relu(concat(fc2 out, fc1 out)) per relation
__device__ float g_z[(size_t)3 * N1v * 128];      // per-relation conv outputs
__device__ float g_t[(size_t)3 * N1v * 128];      // tanh buffer for attention
__device__ float g_h2[(size_t)N2v * 128];
__device__ int   g_cnt[3 * N1v];
__device__ int   g_off[3 * N1v + 1];
__device__ int   g_cur[3 * N1v];
__device__ int   g_sorted[3 * E0v];
__device__ float g_partial[8192];
__device__ float g_beta[4];

// ---------------- SGEMM, N fixed at 128, double-buffered: C = act(A@B + bias) ----------------
// ACT: 0=none, 1=relu, 2=tanh. Batched over blockIdx.y via element strides.
template <int ACT>
__global__ void __launch_bounds__(256) sgemm128(
    const float* __restrict__ A, const float* __restrict__ B,
    const float* __restrict__ bias, float* __restrict__ C,
    int M, int K, int lda, int ldc,
    size_t aStride, size_t bStride, int biasStride, size_t cStride)
{
    __shared__ float As[2][16][132];   // transposed A tile, padded (row = k, 16B-aligned rows)
    __shared__ float Bs[2][16][128];

    const int tid = threadIdx.x;
    A    += (size_t)blockIdx.y * aStride;
    B    += (size_t)blockIdx.y * bStride;
    bias += (size_t)blockIdx.y * biasStride;
    C    += (size_t)blockIdx.y * cStride;

    const int m0 = blockIdx.x * 128;
    const int tx = tid & 15, ty = tid >> 4;

    // A tile: 128 rows x 16 cols; each thread loads 8 consecutive floats of one row
    const int arow = tid >> 1;
    const int acol = (tid & 1) * 8;
    // B tile: 16 rows x 128 cols; each thread loads 8 consecutive floats of one row
    const int brow = tid >> 4;
    const int bcol = (tid & 15) * 8;

    const bool avalid = (m0 + arow) < M;
    const float* Aptr = A + (size_t)(m0 + arow) * lda + acol;
    const float* Bptr = B + (size_t)brow * 128 + bcol;

    float4 pa0, pa1, pb0, pb1;
    if (avalid) { pa0 = *(const float4*)(Aptr); pa1 = *(const float4*)(Aptr + 4); }
    else        { pa0 = make_float4(0.f,0.f,0.f,0.f); pa1 = pa0; }
    pb0 = *(const float4*)(Bptr); pb1 = *(const float4*)(Bptr + 4);

    float acc[8][8];
#pragma unroll
    for (int i = 0; i < 8; i++)
#pragma unroll
        for (int j = 0; j < 8; j++) acc[i][j] = 0.f;

    int buf = 0;
    for (int k0 = 0; k0 < K; k0 += 16) {
        // store prefetched tile
        As[buf][acol + 0][arow] = pa0.x;
        As[buf][acol + 1][arow] = pa0.y;
        As[buf][acol + 2][arow] = pa0.z;
        As[buf][acol + 3][arow] = pa0.w;
        As[buf][acol + 4][arow] = pa1.x;
        As[buf][acol + 5][arow] = pa1.y;
        As[buf][acol + 6][arow] = pa1.z;
        As[buf][acol + 7][arow] = pa1.w;
        *(float4*)&Bs[buf][brow][bcol]     = pb0;
        *(float4*)&Bs[buf][brow][bcol + 4] = pb1;
        __syncthreads();

        // prefetch next tile into registers (overlaps with FFMAs below)
        if (k0 + 16 < K) {
            const float* Ap = Aptr + k0 + 16;
            if (avalid) { pa0 = *(const float4*)(Ap); pa1 = *(const float4*)(Ap + 4); }
            const float* Bp = Bptr + (size_t)(k0 + 16) * 128;
            pb0 = *(const float4*)(Bp); pb1 = *(const float4*)(Bp + 4);
        }

#pragma unroll
        for (int k = 0; k < 16; k++) {
            float4 a0 = *(const float4*)&As[buf][k][ty * 8];
            float4 a1 = *(const float4*)&As[buf][k][ty * 8 + 4];
            float4 b0 = *(const float4*)&Bs[buf][k][tx * 8];
            float4 b1 = *(const float4*)&Bs[buf][k][tx * 8 + 4];
            float ra[8] = {a0.x, a0.y, a0.z, a0.w, a1.x, a1.y, a1.z, a1.w};
            float rb[8] = {b0.x, b0.y, b0.z, b0.w, b1.x, b1.y, b1.z, b1.w};
#pragma unroll
            for (int i = 0; i < 8; i++)
#pragma unroll
                for (int j = 0; j < 8; j++) acc[i][j] = fmaf(ra[i], rb[j], acc[i][j]);
        }
        buf ^= 1;
    }

#pragma unroll
    for (int i = 0; i < 8; i++) {
        int gr = m0 + ty * 8 + i;
        if (gr >= M) continue;
#pragma unroll
        for (int j = 0; j < 8; j += 4) {
            int gc = tx * 8 + j;
            float4 v;
            v.x = acc[i][j + 0] + bias[gc + 0];
            v.y = acc[i][j + 1] + bias[gc + 1];
            v.z = acc[i][j + 2] + bias[gc + 2];
            v.w = acc[i][j + 3] + bias[gc + 3];
            if (ACT == 1) {
                v.x = fmaxf(v.x, 0.f); v.y = fmaxf(v.y, 0.f);
                v.z = fmaxf(v.z, 0.f); v.w = fmaxf(v.w, 0.f);
            } else if (ACT == 2) {
                v.x = tanhf(v.x); v.y = tanhf(v.y); v.z = tanhf(v.z); v.w = tanhf(v.w);
            }
            *(float4*)&C[(size_t)gr * ldc + gc] = v;
        }
    }
}

// ---------------- gather tss/rs into feat cols [128:256) ----------------
__global__ void gather_emb(const float* __restrict__ tss, const float* __restrict__ rs,
                           const int* __restrict__ nid, float* __restrict__ feat, int n)
{
    int i = blockIdx.x * blockDim.x + threadIdx.x;
    int row = i >> 7, c = i & 127;
    if (row < n) {
        int g = nid[row];
        feat[(size_t)row * 256 + 128 + c] = (c < 64) ? tss[(size_t)g * 64 + c]
                                                     : rs[(size_t)g * 64 + (c - 64)];
    }
}

// ---------------- CSR build, 3 relations batched ----------------
__global__ void hist_k(const int* __restrict__ dst, int* __restrict__ cnt, int E, int ndst)
{
    int e = blockIdx.x * blockDim.x + threadIdx.x;
    if (e < 3 * E) atomicAdd(&cnt[(e / E) * ndst + dst[e]], 1);
}

// single-block scan: per-thread sequential + warp-shuffle hierarchy
__global__ void scan_k(const int* __restrict__ cnt, int* __restrict__ off,
                       int* __restrict__ cur, int n)
{
    __shared__ int wsum[32];
    int c = (n + 1023) >> 10;
    int lo = threadIdx.x * c;
    int hi = lo + c; if (hi > n) hi = n;
    int s = 0;
    for (int i = lo; i < hi; i++) s += cnt[i];
    int lane = threadIdx.x & 31, w = threadIdx.x >> 5;
    int v = s;
#pragma unroll
    for (int o = 1; o < 32; o <<= 1) {
        int t = __shfl_up_sync(0xFFFFFFFFu, v, o);
        if (lane >= o) v += t;
    }
    if (lane == 31) wsum[w] = v;
    __syncthreads();
    if (w == 0) {
        int x = wsum[lane];
#pragma unroll
        for (int o = 1; o < 32; o <<= 1) {
            int t = __shfl_up_sync(0xFFFFFFFFu, x, o);
            if (lane >= o) x += t;
        }
        wsum[lane] = x;
    }
    __syncthreads();
    int run = v - s + (w ? wsum[w - 1] : 0);
    for (int i = lo; i < hi; i++) { off[i] = run; cur[i] = run; run += cnt[i]; }
    if (lo < n && hi == n) off[n] = run;
}

__global__ void scatter_k(const int* __restrict__ src, const int* __restrict__ dst,
                          int* __restrict__ cur, int* __restrict__ sorted, int E, int ndst)
{
    int e = blockIdx.x * blockDim.x + threadIdx.x;
    if (e < 3 * E) {
        int p = atomicAdd(&cur[(e / E) * ndst + dst[e]], 1);
        sorted[p] = src[e];
    }
}

// ---------------- aggregation: one block (256 thr) per (relation,dst); deterministic ----------------
__global__ void aggregate_k(const float* __restrict__ feat, const int* __restrict__ off,
                            const int* __restrict__ sorted, float* __restrict__ msg)
{
    __shared__ int idx[1024];
    int b = blockIdx.x;             // r * ndst + d
    int s0 = off[b], s1 = off[b + 1];
    int deg = s1 - s0;
    if (deg > 1024) deg = 1024;
    for (int i = threadIdx.x; i < deg; i += blockDim.x) idx[i] = sorted[s0 + i];
    __syncthreads();
    for (int p = 0; p < deg; p++) {          // odd-even sort -> deterministic order
        for (int j = (p & 1) + 2 * threadIdx.x; j + 1 < deg; j += 2 * blockDim.x) {
            int a = idx[j], bb = idx[j + 1];
            if (a > bb) { idx[j] = bb; idx[j + 1] = a; }
        }
        __syncthreads();
    }
    int c = threadIdx.x;  // feature column 0..255
    float sum = 0.f, mx = -INFINITY;
    for (int i = 0; i < deg; i++) {
        float v = __ldg(&feat[(size_t)idx[i] * 256 + c]);
        sum += v;
        mx = fmaxf(mx, v);
    }
    float mean = deg ? sum / (float)deg : 0.f;
    if (!deg) mx = 0.f;
    size_t base = (size_t)b * 768;
    msg[base + c] = mx;
    msg[base + 256 + c] = mean;
    msg[base + 512 + c] = sum;
}

// ---------------- attention ----------------
__global__ void attn_dot(const float* __restrict__ t, const float* __restrict__ w2,
                         float* __restrict__ partial, int totalrows)
{
    __shared__ float sh[8];
    int warp = threadIdx.x >> 5, lane = threadIdx.x & 31;
    int row = blockIdx.x * 8 + warp;
    float s = 0.f;
    if (row < totalrows) {
        const float* tr = &t[(size_t)row * 128];
        for (int i = lane; i < 128; i += 32) s += tr[i] * w2[i];
    }
    for (int o = 16; o; o >>= 1) s += __shfl_xor_sync(0xFFFFFFFFu, s, o);
    if (!lane) sh[warp] = s;
    __syncthreads();
    if (threadIdx.x == 0) {
        float tot = 0.f;
        for (int i = 0; i < 8; i++) tot += sh[i];
        partial[blockIdx.x] = tot;
    }
}

__global__ void attn_fin(const float* __restrict__ partial, int bpr, float invN,
                         float* __restrict__ beta)
{
    __shared__ float sh[256];
    __shared__ float w[3];
    for (int r = 0; r < 3; r++) {
        float s = 0.f;
        for (int i = threadIdx.x; i < bpr; i += 256) s += partial[r * bpr + i];
        sh[threadIdx.x] = s;
        __syncthreads();
        for (int o = 128; o; o >>= 1) {
            if (threadIdx.x < o) sh[threadIdx.x] += sh[threadIdx.x + o];
            __syncthreads();
        }
        if (threadIdx.x == 0) w[r] = sh[0] * invN;
        __syncthreads();
    }
    if (threadIdx.x == 0) {
        float m = fmaxf(w[0], fmaxf(w[1], w[2]));
        float e0 = expf(w[0] - m), e1 = expf(w[1] - m), e2 = expf(w[2] - m);
        float inv = 1.f / (e0 + e1 + e2);
        beta[0] = e0 * inv; beta[1] = e1 * inv; beta[2] = e2 * inv;
    }
}

__global__ void combine_k(const float* __restrict__ z, const float* __restrict__ beta,
                          float* __restrict__ outf, int n, int zstride, int ldc, int do_relu)
{
    int i = blockIdx.x * blockDim.x + threadIdx.x;
    int row = i >> 7, c = i & 127;
    if (row < n) {
        size_t o = (size_t)row * 128 + c;
        float v = beta[0] * z[o] + beta[1] * z[o + (size_t)zstride]
                + beta[2] * z[o + 2 * (size_t)zstride];
        if (do_relu) v = fmaxf(v, 0.f);
        outf[(size_t)row * ldc + c] = v;
    }
}

// ---------------- predictor ----------------
__global__ void pred_k(const float* __restrict__ h, const float* __restrict__ w,
                       const float* __restrict__ b, float* __restrict__ out, int n)
{
    int gwarp = (blockIdx.x * blockDim.x + threadIdx.x) >> 5;
    int lane = threadIdx.x & 31;
    if (gwarp < n) {
        const float* hr = &h[(size_t)gwarp * 128];
        float s = 0.f;
        for (int i = lane; i < 128; i += 32) s += hr[i] * w[i];
        for (int o = 16; o; o >>= 1) s += __shfl_xor_sync(0xFFFFFFFFu, s, o);
        if (!lane) out[gwarp] = 1.f / (1.f + expf(-(s + b[0])));
    }
}

// ---------------- host orchestration ----------------
static inline int cdiv(int a, int b) { return (a + b - 1) / b; }

extern "C" void kernel_launch(void* const* d_in, const int* in_sizes, int n_in,
                              void* d_out, int out_size)
{
    const float* x_user   = (const float*)d_in[0];
    const float* tss      = (const float*)d_in[1];
    const float* rs       = (const float*)d_in[2];
    const int*   src_nid0 = (const int*)d_in[3];
    const int*   src_nid1 = (const int*)d_in[4];
    const int*   e0_src   = (const int*)d_in[5];
    const int*   e0_dst   = (const int*)d_in[6];
    const int*   e1_src   = (const int*)d_in[7];
    const int*   e1_dst   = (const int*)d_in[8];
    const float* embed_w  = (const float*)d_in[9];
    const float* embed_b  = (const float*)d_in[10];
    const float* attn_w1  = (const float*)d_in[23];
    const float* attn_b1  = (const float*)d_in[24];
    const float* attn_w2  = (const float*)d_in[25];
    const float* pred_w   = (const float*)d_in[26];
    const float* pred_b   = (const float*)d_in[27];
    float* out = (float*)d_out;

    float *feat0, *feat1, *msg, *inp, *z, *t, *h2, *partial, *beta;
    int *cnt, *off, *cur, *sorted;
    cudaGetSymbolAddress((void**)&feat0, g_feat0);
    cudaGetSymbolAddress((void**)&feat1, g_feat1);
    cudaGetSymbolAddress((void**)&msg, g_msg);
    cudaGetSymbolAddress((void**)&inp, g_inp);
    cudaGetSymbolAddress((void**)&z, g_z);
    cudaGetSymbolAddress((void**)&t, g_t);
    cudaGetSymbolAddress((void**)&h2, g_h2);
    cudaGetSymbolAddress((void**)&partial, g_partial);
    cudaGetSymbolAddress((void**)&beta, g_beta);
    cudaGetSymbolAddress((void**)&cnt, g_cnt);
    cudaGetSymbolAddress((void**)&off, g_off);
    cudaGetSymbolAddress((void**)&cur, g_cur);
    cudaGetSymbolAddress((void**)&sorted, g_sorted);

    // feat0 = [x_user @ embed_w + b | tss[src_nid0] | rs[src_nid0]]
    sgemm128<0><<<dim3(cdiv(N0v, 128), 1), 256>>>(x_user, embed_w, embed_b, feat0,
                                                  N0v, 128, 128, 256, 0, 0, 0, 0);
    gather_emb<<<cdiv(N0v * 128, 256), 256>>>(tss, rs, src_nid0, feat0, N0v);

    for (int layer = 0; layer < 2; layer++) {
        const int E = layer ? E1v : E0v;
        const int ndst = layer ? N2v : N1v;
        const int* esrc = layer ? e1_src : e0_src;
        const int* edst = layer ? e1_dst : e0_dst;
        const float* srcfeat = layer ? feat1 : feat0;
        const float* fc1w = (const float*)d_in[11 + layer * 6];
        const float* fc1b = (const float*)d_in[12 + layer * 6];
        const float* fc2w = (const float*)d_in[13 + layer * 6];
        const float* fc2b = (const float*)d_in[14 + layer * 6];
        const float* fc3w = (const float*)d_in[15 + layer * 6];
        const float* fc3b = (const float*)d_in[16 + layer * 6];

        // --- batched CSR build + aggregation over all 3 relations ---
        cudaMemsetAsync(cnt, 0, 3 * ndst * sizeof(int));
        hist_k<<<cdiv(3 * E, 256), 256>>>(edst, cnt, E, ndst);
        scan_k<<<1, 1024>>>(cnt, off, cur, 3 * ndst);
        scatter_k<<<cdiv(3 * E, 256), 256>>>(esrc, edst, cur, sorted, E, ndst);
        aggregate_k<<<3 * ndst, 256>>>(srcfeat, off, sorted, msg);

        // --- batched per-relation GEMMs ---
        // inp[r][:,0:128]   = relu(msg[r] @ fc2w[r] + b2)
        sgemm128<1><<<dim3(cdiv(ndst, 128), 3), 256>>>(
            msg, fc2w, fc2b, inp, ndst, 768, 768, 256,
            (size_t)ndst * 768, (size_t)768 * 128, 128, (size_t)ndst * 256);
        // inp[r][:,128:256] = relu(dstfeat @ fc1w[r] + b1)   (A shared: aStride = 0)
        sgemm128<1><<<dim3(cdiv(ndst, 128), 3), 256>>>(
            srcfeat, fc1w, fc1b, inp + 128, ndst, 256, 256, 256,
            0, (size_t)256 * 128, 128, (size_t)ndst * 256);
        // z[r] = inp[r] @ fc3w[r] + b3
        sgemm128<0><<<dim3(cdiv(ndst, 128), 3), 256>>>(
            inp, fc3w, fc3b, z, ndst, 256, 256, 128,
            (size_t)ndst * 256, (size_t)256 * 128, 128, (size_t)ndst * 128);

        // --- semantic attention over z [3, ndst, 128] ---
        int rows = 3 * ndst;
        sgemm128<2><<<dim3(cdiv(rows, 128), 1), 256>>>(
            z, attn_w1, attn_b1, t, rows, 128, 128, 128, 0, 0, 0, 0);
        attn_dot<<<rows / 8, 256>>>(t, attn_w2, partial, rows);
        attn_fin<<<1, 256>>>(partial, ndst / 8, 1.f / (float)ndst, beta);

        if (layer == 0) {
            combine_k<<<cdiv(ndst * 128, 256), 256>>>(z, beta, feat1, ndst, ndst * 128, 256, 1);
            gather_emb<<<cdiv(ndst * 128, 256), 256>>>(tss, rs, src_nid1, feat1, ndst);
        } else {
            combine_k<<<cdiv(ndst * 128, 256), 256>>>(z, beta, h2, ndst, ndst * 128, 128, 0);
        }
    }

    pred_k<<<cdiv(N2v * 32, 256), 256>>>(h2, pred_w, pred_b, out, N2v);
}

// round 4
// speedup vs baseline: 2.0051x; 1.3058x over previous
#include <cuda_runtime.h>
#include <cuda_bf16.h>
#include <math.h>
#include <stdint.h>

// ---------------- problem constants ----------------
#define N0v 100000
#define N1v 20000
#define N2v 4000
#define E0v 160000
#define E1v 64000

// ---------------- device scratch ----------------
__device__ float g_feat0[(size_t)N0v * 256];
__device__ float g_feat1[(size_t)N1v * 256];
__device__ float g_msg[(size_t)3 * N1v * 768];
__device__ float g_inp[(size_t)3 * N1v * 256];
__device__ float g_z[(size_t)3 * N1v * 128];
__device__ float g_t[(size_t)3 * N1v * 128];
__device__ float g_h2[(size_t)N2v * 128];
__device__ int   g_cnt[3 * N1v];
__device__ int   g_off[3 * N1v + 1];
__device__ int   g_cur[3 * N1v];
__device__ int   g_sorted[3 * E0v];
__device__ int   g_bsum[128];
__device__ float g_partial[8192];
__device__ float g_beta[4];
__device__ __nv_bfloat16 g_bth[1016832];  // pre-transposed weights hi, K-major [128,K]
__device__ __nv_bfloat16 g_btl[1016832];  // lo parts

// Bt offsets (elements)
#define BT_EMBED 0
#define BT_ATTN  16384
#define BT_L1F1  32768
#define BT_L1F2  131072
#define BT_L1F3  425984
#define BT_L2F1  524288
#define BT_L2F2  622592
#define BT_L2F3  917504

__device__ __forceinline__ uint32_t smem_u32(const void* p) {
    uint32_t a;
    asm("{ .reg .u64 t; cvta.to.shared.u64 t, %1; cvt.u32.u64 %0, t; }" : "=r"(a) : "l"(p));
    return a;
}

__device__ __forceinline__ void mma_bf16(float* d, const uint32_t* a, const uint32_t* b) {
    asm volatile(
        "mma.sync.aligned.m16n8k16.row.col.f32.bf16.bf16.f32 "
        "{%0,%1,%2,%3},{%4,%5,%6,%7},{%8,%9},{%0,%1,%2,%3};"
        : "+f"(d[0]), "+f"(d[1]), "+f"(d[2]), "+f"(d[3])
        : "r"(a[0]), "r"(a[1]), "r"(a[2]), "r"(a[3]), "r"(b[0]), "r"(b[1]));
}
__device__ __forceinline__ void ldsm_x4(uint32_t* r, uint32_t addr) {
    asm volatile("ldmatrix.sync.aligned.m8n8.x4.shared.b16 {%0,%1,%2,%3}, [%4];"
        : "=r"(r[0]), "=r"(r[1]), "=r"(r[2]), "=r"(r[3]) : "r"(addr));
}
__device__ __forceinline__ void ldsm_x2(uint32_t* r, uint32_t addr) {
    asm volatile("ldmatrix.sync.aligned.m8n8.x2.shared.b16 {%0,%1}, [%2];"
        : "=r"(r[0]), "=r"(r[1]) : "r"(addr));
}

// ---------------- weight prep: transpose [K,128] fp32 -> [128,K] bf16 hi/lo ----------------
__global__ void prep_bt(const float* __restrict__ W, __nv_bfloat16* __restrict__ bh,
                        __nv_bfloat16* __restrict__ bl, int K, size_t wStr, size_t oStr)
{
    W  += (size_t)blockIdx.y * wStr;
    bh += (size_t)blockIdx.y * oStr;
    bl += (size_t)blockIdx.y * oStr;
    int i = blockIdx.x * 256 + threadIdx.x;
    if (i < 128 * K) {
        int n = i / K, k = i - n * K;
        float v = W[(size_t)k * 128 + n];
        __nv_bfloat16 h = __float2bfloat16(v);
        bh[i] = h;
        bl[i] = __float2bfloat16(v - __bfloat162float(h));
    }
}

// ---------------- HGEMM (mma.sync bf16, 3-term split): C[M,128] = act(A@B + bias) ----------------
// A fp32 [M,K] (lda); B pre-split bf16 [128,K] K-major. ACT: 0=none,1=relu,2=tanh.
// Batched over blockIdx.y via strides. CTA: 256 thr = 8 warps (4x2), tile 128x128, BK=32.
#define PAD 40   // smem row stride in halves (bank-conflict-free for ldmatrix)

template <int ACT>
__global__ void __launch_bounds__(256) hgemm(
    const float* __restrict__ A, const __nv_bfloat16* __restrict__ Bh,
    const __nv_bfloat16* __restrict__ Bl, const float* __restrict__ bias,
    float* __restrict__ C, int M, int K, int lda, int ldc,
    size_t aStr, size_t bStr, int biasStr, size_t cStr)
{
    __shared__ __align__(16) __nv_bfloat16 sAh[128 * PAD];
    __shared__ __align__(16) __nv_bfloat16 sAl[128 * PAD];
    __shared__ __align__(16) __nv_bfloat16 sBh[128 * PAD];
    __shared__ __align__(16) __nv_bfloat16 sBl[128 * PAD];

    const int tid = threadIdx.x, wid = tid >> 5, lane = tid & 31;
    const int wm = wid & 3, wn = wid >> 2;            // warp tile: rows 32*wm, cols 64*wn

    A    += (size_t)blockIdx.y * aStr;
    Bh   += (size_t)blockIdx.y * bStr;
    Bl   += (size_t)blockIdx.y * bStr;
    bias += (size_t)blockIdx.y * biasStr;
    C    += (size_t)blockIdx.y * cStr;
    const int m0 = blockIdx.x * 128;

    float acc[2][8][4];
#pragma unroll
    for (int i = 0; i < 2; i++)
#pragma unroll
        for (int j = 0; j < 8; j++)
#pragma unroll
            for (int q = 0; q < 4; q++) acc[i][j][q] = 0.f;

    // ldmatrix source addresses (per lane)
    const int a_m = (lane & 7) + ((lane >> 3) & 1) * 8;     // x4: matrix pair (m, m+8)
    const int a_k = (lane >> 4) * 8;                        //     then k+8
    const int bln = lane & 15;
    const int b_n = bln & 7;                                // x2: n row
    const int b_k = ((bln >> 3) & 1) * 8;                   //     matrix1 = k+8

    for (int k0 = 0; k0 < K; k0 += 32) {
        // --- load A tile [128 x 32] fp32, split to bf16 hi/lo ---
#pragma unroll
        for (int l = 0; l < 4; l++) {
            int f = tid + l * 256;                 // 1024 float4 jobs
            int r = f >> 3, c4 = (f & 7) * 4;
            float4 v = make_float4(0.f, 0.f, 0.f, 0.f);
            if (m0 + r < M)
                v = *(const float4*)(A + (size_t)(m0 + r) * lda + k0 + c4);
            __nv_bfloat16 h0 = __float2bfloat16(v.x), h1 = __float2bfloat16(v.y);
            __nv_bfloat16 h2 = __float2bfloat16(v.z), h3 = __float2bfloat16(v.w);
            __nv_bfloat16 l0 = __float2bfloat16(v.x - __bfloat162float(h0));
            __nv_bfloat16 l1 = __float2bfloat16(v.y - __bfloat162float(h1));
            __nv_bfloat16 l2 = __float2bfloat16(v.z - __bfloat162float(h2));
            __nv_bfloat16 l3 = __float2bfloat16(v.w - __bfloat162float(h3));
            uint2 hp = make_uint2(((uint32_t)__bfloat16_as_ushort(h1) << 16) | __bfloat16_as_ushort(h0),
                                  ((uint32_t)__bfloat16_as_ushort(h3) << 16) | __bfloat16_as_ushort(h2));
            uint2 lp = make_uint2(((uint32_t)__bfloat16_as_ushort(l1) << 16) | __bfloat16_as_ushort(l0),
                                  ((uint32_t)__bfloat16_as_ushort(l3) << 16) | __bfloat16_as_ushort(l2));
            *(uint2*)&sAh[r * PAD + c4] = hp;
            *(uint2*)&sAl[r * PAD + c4] = lp;
        }
        // --- load B tiles [128 x 32] bf16 hi/lo (16B chunks) ---
#pragma unroll
        for (int l = 0; l < 2; l++) {
            int f = tid + l * 256;                 // 512 jobs
            int r = f >> 2, ch = (f & 3) * 8;
            size_t g = (size_t)r * K + k0 + ch;
            *(uint4*)&sBh[r * PAD + ch] = *(const uint4*)(Bh + g);
            *(uint4*)&sBl[r * PAD + ch] = *(const uint4*)(Bl + g);
        }
        __syncthreads();

#pragma unroll
        for (int ks = 0; ks < 2; ks++) {
            const int kk = ks * 16;
            uint32_t ah[2][4], al[2][4];
#pragma unroll
            for (int mt = 0; mt < 2; mt++) {
                int mrow = wm * 32 + mt * 16 + a_m;
                ldsm_x4(ah[mt], smem_u32(&sAh[mrow * PAD + kk + a_k]));
                ldsm_x4(al[mt], smem_u32(&sAl[mrow * PAD + kk + a_k]));
            }
#pragma unroll
            for (int nt = 0; nt < 8; nt++) {
                int nrow = wn * 64 + nt * 8 + b_n;
                uint32_t bh[2], bl[2];
                ldsm_x2(bh, smem_u32(&sBh[nrow * PAD + kk + b_k]));
                ldsm_x2(bl, smem_u32(&sBl[nrow * PAD + kk + b_k]));
#pragma unroll
                for (int mt = 0; mt < 2; mt++) {
                    mma_bf16(acc[mt][nt], ah[mt], bh);
                    mma_bf16(acc[mt][nt], ah[mt], bl);
                    mma_bf16(acc[mt][nt], al[mt], bh);
                }
            }
        }
        __syncthreads();
    }

    // --- epilogue: frag (r=lane/4, c=2*(lane%4)); rows r, r+8 ---
    const int fr = lane >> 2, fc = (lane & 3) * 2;
#pragma unroll
    for (int mt = 0; mt < 2; mt++) {
#pragma unroll
        for (int half = 0; half < 2; half++) {
            int gr = m0 + wm * 32 + mt * 16 + fr + half * 8;
            if (gr >= M) continue;
#pragma unroll
            for (int nt = 0; nt < 8; nt++) {
                int gc = wn * 64 + nt * 8 + fc;
                float2 v;
                v.x = acc[mt][nt][half * 2 + 0] + bias[gc + 0];
                v.y = acc[mt][nt][half * 2 + 1] + bias[gc + 1];
                if (ACT == 1) { v.x = fmaxf(v.x, 0.f); v.y = fmaxf(v.y, 0.f); }
                else if (ACT == 2) { v.x = tanhf(v.x); v.y = tanhf(v.y); }
                *(float2*)(C + (size_t)gr * ldc + gc) = v;
            }
        }
    }
}

// ---------------- gather tss/rs into feat cols [128:256) ----------------
__global__ void gather_emb(const float* __restrict__ tss, const float* __restrict__ rs,
                           const int* __restrict__ nid, float* __restrict__ feat, int n)
{
    int i = blockIdx.x * blockDim.x + threadIdx.x;
    int row = i >> 7, c = i & 127;
    if (row < n) {
        int g = nid[row];
        feat[(size_t)row * 256 + 128 + c] = (c < 64) ? tss[(size_t)g * 64 + c]
                                                     : rs[(size_t)g * 64 + (c - 64)];
    }
}

// ---------------- CSR build (3 relations batched) ----------------
__global__ void hist_k(const int* __restrict__ dst, int* __restrict__ cnt, int E, int ndst)
{
    int e = blockIdx.x * blockDim.x + threadIdx.x;
    if (e < 3 * E) atomicAdd(&cnt[(e / E) * ndst + dst[e]], 1);
}

__global__ void scan_part(const int* __restrict__ cnt, int* __restrict__ off,
                          int* __restrict__ bsum, int n)
{
    __shared__ int ws[32];
    int tid = threadIdx.x, lane = tid & 31, w = tid >> 5;
    int i = blockIdx.x * 1024 + tid;
    int v = (i < n) ? cnt[i] : 0;
    int x = v;
#pragma unroll
    for (int o = 1; o < 32; o <<= 1) {
        int t = __shfl_up_sync(0xFFFFFFFFu, x, o);
        if (lane >= o) x += t;
    }
    if (lane == 31) ws[w] = x;
    __syncthreads();
    if (w == 0) {
        int y = ws[lane];
#pragma unroll
        for (int o = 1; o < 32; o <<= 1) {
            int t = __shfl_up_sync(0xFFFFFFFFu, y, o);
            if (lane >= o) y += t;
        }
        ws[lane] = y;
    }
    __syncthreads();
    int excl = x - v + (w ? ws[w - 1] : 0);
    if (i < n) off[i] = excl;
    if (tid == 1023) bsum[blockIdx.x] = excl + v;
}

__global__ void scan_bs(int* __restrict__ bsum, int* __restrict__ off, int nb, int n)
{
    __shared__ int sh[64];
    int tid = threadIdx.x;
    int v = (tid < nb) ? bsum[tid] : 0;
    sh[tid] = v;
    __syncthreads();
    for (int d = 1; d < 64; d <<= 1) {
        int t = (tid >= d) ? sh[tid - d] : 0;
        __syncthreads();
        sh[tid] += t;
        __syncthreads();
    }
    if (tid < nb) bsum[tid] = sh[tid] - v;   // exclusive
    if (tid == 0) off[n] = sh[63];
}

__global__ void scan_add(int* __restrict__ off, const int* __restrict__ bsum,
                         int* __restrict__ cur, int n)
{
    int i = blockIdx.x * 1024 + threadIdx.x;
    if (i < n) {
        int o = off[i] + bsum[blockIdx.x];
        off[i] = o;
        cur[i] = o;
    }
}

__global__ void scatter_k(const int* __restrict__ src, const int* __restrict__ dst,
                          int* __restrict__ cur, int* __restrict__ sorted, int E, int ndst)
{
    int e = blockIdx.x * blockDim.x + threadIdx.x;
    if (e < 3 * E) {
        int p = atomicAdd(&cur[(e / E) * ndst + dst[e]], 1);
        sorted[p] = src[e];
    }
}

// ---------------- aggregation: one block per (relation,dst); deterministic ----------------
__global__ void aggregate_k(const float* __restrict__ feat, const int* __restrict__ off,
                            const int* __restrict__ sorted, float* __restrict__ msg)
{
    __shared__ int idx[1024];
    int b = blockIdx.x;
    int s0 = off[b], s1 = off[b + 1];
    int deg = s1 - s0;
    if (deg > 1024) deg = 1024;
    for (int i = threadIdx.x; i < deg; i += blockDim.x) idx[i] = sorted[s0 + i];
    __syncthreads();
    for (int p = 0; p < deg; p++) {
        for (int j = (p & 1) + 2 * threadIdx.x; j + 1 < deg; j += 2 * blockDim.x) {
            int a = idx[j], bb = idx[j + 1];
            if (a > bb) { idx[j] = bb; idx[j + 1] = a; }
        }
        __syncthreads();
    }
    int c = threadIdx.x;
    float sum = 0.f, mx = -INFINITY;
    for (int i = 0; i < deg; i++) {
        float v = __ldg(&feat[(size_t)idx[i] * 256 + c]);
        sum += v;
        mx = fmaxf(mx, v);
    }
    float mean = deg ? sum / (float)deg : 0.f;
    if (!deg) mx = 0.f;
    size_t base = (size_t)b * 768;
    msg[base + c] = mx;
    msg[base + 256 + c] = mean;
    msg[base + 512 + c] = sum;
}

// ---------------- attention ----------------
__global__ void attn_dot(const float* __restrict__ t, const float* __restrict__ w2,
                         float* __restrict__ partial, int totalrows)
{
    __shared__ float sh[8];
    int warp = threadIdx.x >> 5, lane = threadIdx.x & 31;
    int row = blockIdx.x * 8 + warp;
    float s = 0.f;
    if (row < totalrows) {
        const float* tr = &t[(size_t)row * 128];
        for (int i = lane; i < 128; i += 32) s += tr[i] * w2[i];
    }
    for (int o = 16; o; o >>= 1) s += __shfl_xor_sync(0xFFFFFFFFu, s, o);
    if (!lane) sh[warp] = s;
    __syncthreads();
    if (threadIdx.x == 0) {
        float tot = 0.f;
        for (int i = 0; i < 8; i++) tot += sh[i];
        partial[blockIdx.x] = tot;
    }
}

__global__ void attn_fin(const float* __restrict__ partial, int bpr, float invN,
                         float* __restrict__ beta)
{
    __shared__ float sh[256];
    __shared__ float w[3];
    for (int r = 0; r < 3; r++) {
        float s = 0.f;
        for (int i = threadIdx.x; i < bpr; i += 256) s += partial[r * bpr + i];
        sh[threadIdx.x] = s;
        __syncthreads();
        for (int o = 128; o; o >>= 1) {
            if (threadIdx.x < o) sh[threadIdx.x] += sh[threadIdx.x + o];
            __syncthreads();
        }
        if (threadIdx.x == 0) w[r] = sh[0] * invN;
        __syncthreads();
    }
    if (threadIdx.x == 0) {
        float m = fmaxf(w[0], fmaxf(w[1], w[2]));
        float e0 = expf(w[0] - m), e1 = expf(w[1] - m), e2 = expf(w[2] - m);
        float inv = 1.f / (e0 + e1 + e2);
        beta[0] = e0 * inv; beta[1] = e1 * inv; beta[2] = e2 * inv;
    }
}

__global__ void combine_k(const float* __restrict__ z, const float* __restrict__ beta,
                          float* __restrict__ outf, int n, int zstride, int ldc, int do_relu)
{
    int i = blockIdx.x * blockDim.x + threadIdx.x;
    int row = i >> 7, c = i & 127;
    if (row < n) {
        size_t o = (size_t)row * 128 + c;
        float v = beta[0] * z[o] + beta[1] * z[o + (size_t)zstride]
                + beta[2] * z[o + 2 * (size_t)zstride];
        if (do_relu) v = fmaxf(v, 0.f);
        outf[(size_t)row * ldc + c] = v;
    }
}

__global__ void pred_k(const float* __restrict__ h, const float* __restrict__ w,
                       const float* __restrict__ b, float* __restrict__ out, int n)
{
    int gwarp = (blockIdx.x * blockDim.x + threadIdx.x) >> 5;
    int lane = threadIdx.x & 31;
    if (gwarp < n) {
        const float* hr = &h[(size_t)gwarp * 128];
        float s = 0.f;
        for (int i = lane; i < 128; i += 32) s += hr[i] * w[i];
        for (int o = 16; o; o >>= 1) s += __shfl_xor_sync(0xFFFFFFFFu, s, o);
        if (!lane) out[gwarp] = 1.f / (1.f + expf(-(s + b[0])));
    }
}

// ---------------- host orchestration ----------------
static inline int cdiv(int a, int b) { return (a + b - 1) / b; }

extern "C" void kernel_launch(void* const* d_in, const int* in_sizes, int n_in,
                              void* d_out, int out_size)
{
    const float* x_user   = (const float*)d_in[0];
    const float* tss      = (const float*)d_in[1];
    const float* rs       = (const float*)d_in[2];
    const int*   src_nid0 = (const int*)d_in[3];
    const int*   src_nid1 = (const int*)d_in[4];
    const int*   e0_src   = (const int*)d_in[5];
    const int*   e0_dst   = (const int*)d_in[6];
    const int*   e1_src   = (const int*)d_in[7];
    const int*   e1_dst   = (const int*)d_in[8];
    const float* embed_w  = (const float*)d_in[9];
    const float* embed_b  = (const float*)d_in[10];
    const float* attn_w1  = (const float*)d_in[23];
    const float* attn_b1  = (const float*)d_in[24];
    const float* attn_w2  = (const float*)d_in[25];
    const float* pred_w   = (const float*)d_in[26];
    const float* pred_b   = (const float*)d_in[27];
    float* out = (float*)d_out;

    float *feat0, *feat1, *msg, *inp, *z, *t, *h2, *partial, *beta;
    int *cnt, *off, *cur, *sorted, *bsum;
    __nv_bfloat16 *bth, *btl;
    cudaGetSymbolAddress((void**)&feat0, g_feat0);
    cudaGetSymbolAddress((void**)&feat1, g_feat1);
    cudaGetSymbolAddress((void**)&msg, g_msg);
    cudaGetSymbolAddress((void**)&inp, g_inp);
    cudaGetSymbolAddress((void**)&z, g_z);
    cudaGetSymbolAddress((void**)&t, g_t);
    cudaGetSymbolAddress((void**)&h2, g_h2);
    cudaGetSymbolAddress((void**)&partial, g_partial);
    cudaGetSymbolAddress((void**)&beta, g_beta);
    cudaGetSymbolAddress((void**)&cnt, g_cnt);
    cudaGetSymbolAddress((void**)&off, g_off);
    cudaGetSymbolAddress((void**)&cur, g_cur);
    cudaGetSymbolAddress((void**)&sorted, g_sorted);
    cudaGetSymbolAddress((void**)&bsum, g_bsum);
    cudaGetSymbolAddress((void**)&bth, g_bth);
    cudaGetSymbolAddress((void**)&btl, g_btl);

    // --- weight prep: transpose + bf16 hi/lo split ---
    prep_bt<<<dim3(cdiv(128 * 128, 256), 1), 256>>>(embed_w, bth + BT_EMBED, btl + BT_EMBED, 128, 0, 0);
    prep_bt<<<dim3(cdiv(128 * 128, 256), 1), 256>>>(attn_w1, bth + BT_ATTN, btl + BT_ATTN, 128, 0, 0);
    for (int layer = 0; layer < 2; layer++) {
        const float* fc1w = (const float*)d_in[11 + layer * 6];
        const float* fc2w = (const float*)d_in[13 + layer * 6];
        const float* fc3w = (const float*)d_in[15 + layer * 6];
        size_t o1 = layer ? BT_L2F1 : BT_L1F1;
        size_t o2 = layer ? BT_L2F2 : BT_L1F2;
        size_t o3 = layer ? BT_L2F3 : BT_L1F3;
        prep_bt<<<dim3(cdiv(128 * 256, 256), 3), 256>>>(fc1w, bth + o1, btl + o1, 256,
                                                        (size_t)256 * 128, (size_t)128 * 256);
        prep_bt<<<dim3(cdiv(128 * 768, 256), 3), 256>>>(fc2w, bth + o2, btl + o2, 768,
                                                        (size_t)768 * 128, (size_t)128 * 768);
        prep_bt<<<dim3(cdiv(128 * 256, 256), 3), 256>>>(fc3w, bth + o3, btl + o3, 256,
                                                        (size_t)256 * 128, (size_t)128 * 256);
    }

    // feat0 = [x_user @ embed_w + b | tss[src_nid0] | rs[src_nid0]]
    hgemm<0><<<dim3(cdiv(N0v, 128), 1), 256>>>(
        x_user, bth + BT_EMBED, btl + BT_EMBED, embed_b, feat0,
        N0v, 128, 128, 256, 0, 0, 0, 0);
    gather_emb<<<cdiv(N0v * 128, 256), 256>>>(tss, rs, src_nid0, feat0, N0v);

    for (int layer = 0; layer < 2; layer++) {
        const int E = layer ? E1v : E0v;
        const int ndst = layer ? N2v : N1v;
        const int* esrc = layer ? e1_src : e0_src;
        const int* edst = layer ? e1_dst : e0_dst;
        const float* srcfeat = layer ? feat1 : feat0;
        const float* fc1b = (const float*)d_in[12 + layer * 6];
        const float* fc2b = (const float*)d_in[14 + layer * 6];
        const float* fc3b = (const float*)d_in[16 + layer * 6];
        size_t o1 = layer ? BT_L2F1 : BT_L1F1;
        size_t o2 = layer ? BT_L2F2 : BT_L1F2;
        size_t o3 = layer ? BT_L2F3 : BT_L1F3;

        // --- batched CSR build + aggregation ---
        int n = 3 * ndst;
        int nb = cdiv(n, 1024);
        cudaMemsetAsync(cnt, 0, n * sizeof(int));
        hist_k<<<cdiv(3 * E, 256), 256>>>(edst, cnt, E, ndst);
        scan_part<<<nb, 1024>>>(cnt, off, bsum, n);
        scan_bs<<<1, 64>>>(bsum, off, nb, n);
        scan_add<<<nb, 1024>>>(off, bsum, cur, n);
        scatter_k<<<cdiv(3 * E, 256), 256>>>(esrc, edst, cur, sorted, E, ndst);
        aggregate_k<<<n, 256>>>(srcfeat, off, sorted, msg);

        // --- per-relation GEMMs (batched over blockIdx.y) ---
        hgemm<1><<<dim3(cdiv(ndst, 128), 3), 256>>>(
            msg, bth + o2, btl + o2, fc2b, inp, ndst, 768, 768, 256,
            (size_t)ndst * 768, (size_t)128 * 768, 128, (size_t)ndst * 256);
        hgemm<1><<<dim3(cdiv(ndst, 128), 3), 256>>>(
            srcfeat, bth + o1, btl + o1, fc1b, inp + 128, ndst, 256, 256, 256,
            0, (size_t)128 * 256, 128, (size_t)ndst * 256);
        hgemm<0><<<dim3(cdiv(ndst, 128), 3), 256>>>(
            inp, bth + o3, btl + o3, fc3b, z, ndst, 256, 256, 128,
            (size_t)ndst * 256, (size_t)128 * 256, 128, (size_t)ndst * 128);

        // --- semantic attention ---
        int rows = 3 * ndst;
        hgemm<2><<<dim3(cdiv(rows, 128), 1), 256>>>(
            z, bth + BT_ATTN, btl + BT_ATTN, attn_b1, t, rows, 128, 128, 128, 0, 0, 0, 0);
        attn_dot<<<rows / 8, 256>>>(t, attn_w2, partial, rows);
        attn_fin<<<1, 256>>>(partial, ndst / 8, 1.f / (float)ndst, beta);

        if (layer == 0) {
            combine_k<<<cdiv(ndst * 128, 256), 256>>>(z, beta, feat1, ndst, ndst * 128, 256, 1);
            gather_emb<<<cdiv(ndst * 128, 256), 256>>>(tss, rs, src_nid1, feat1, ndst);
        } else {
            combine_k<<<cdiv(ndst * 128, 256), 256>>>(z, beta, h2, ndst, ndst * 128, 128, 0);
        }
    }

    pred_k<<<cdiv(N2v * 32, 256), 256>>>(h2, pred_w, pred_b, out, N2v);
}

// round 5
// speedup vs baseline: 3.3843x; 1.6879x over previous
#include <cuda_runtime.h>
#include <cuda_fp16.h>
#include <math.h>
#include <stdint.h>

// ---------------- problem constants ----------------
#define N0v 100000
#define N1v 20000
#define N2v 4000
#define E0v 160000
#define E1v 64000

// ---------------- device scratch ----------------
__device__ __half g_feat0[(size_t)N0v * 256];
__device__ __half g_feat1[(size_t)N1v * 256];
__device__ __half g_msg[(size_t)3 * N1v * 768];
__device__ __half g_inp[(size_t)3 * N1v * 256];
__device__ float  g_z[(size_t)3 * N1v * 128];
__device__ float  g_t[(size_t)3 * N1v * 128];
__device__ float  g_h2[(size_t)N2v * 128];
__device__ int    g_cnt[3 * N1v];
__device__ int    g_off[3 * N1v + 1];
__device__ int    g_cur[3 * N1v];
__device__ int    g_sorted[3 * E0v];
__device__ int    g_bsum[128];
__device__ float  g_partial[8192];
__device__ float  g_beta[4];
__device__ __half g_bt[1016832];   // pre-transposed weights fp16, K-major [128,K]

// Bt offsets (elements)
#define BT_EMBED 0
#define BT_ATTN  16384
#define BT_L1F1  32768
#define BT_L1F2  131072
#define BT_L1F3  425984
#define BT_L2F1  524288
#define BT_L2F2  622592
#define BT_L2F3  917504

__device__ __forceinline__ uint32_t smem_u32(const void* p) {
    uint32_t a;
    asm("{ .reg .u64 t; cvta.to.shared.u64 t, %1; cvt.u32.u64 %0, t; }" : "=r"(a) : "l"(p));
    return a;
}
__device__ __forceinline__ void mma_f16(float* d, const uint32_t* a, const uint32_t* b) {
    asm volatile(
        "mma.sync.aligned.m16n8k16.row.col.f32.f16.f16.f32 "
        "{%0,%1,%2,%3},{%4,%5,%6,%7},{%8,%9},{%0,%1,%2,%3};"
        : "+f"(d[0]), "+f"(d[1]), "+f"(d[2]), "+f"(d[3])
        : "r"(a[0]), "r"(a[1]), "r"(a[2]), "r"(a[3]), "r"(b[0]), "r"(b[1]));
}
__device__ __forceinline__ void ldsm_x4(uint32_t* r, uint32_t addr) {
    asm volatile("ldmatrix.sync.aligned.m8n8.x4.shared.b16 {%0,%1,%2,%3}, [%4];"
        : "=r"(r[0]), "=r"(r[1]), "=r"(r[2]), "=r"(r[3]) : "r"(addr));
}
__device__ __forceinline__ void ldsm_x2(uint32_t* r, uint32_t addr) {
    asm volatile("ldmatrix.sync.aligned.m8n8.x2.shared.b16 {%0,%1}, [%2];"
        : "=r"(r[0]), "=r"(r[1]) : "r"(addr));
}

// ---------------- weight prep: transpose [K,128] fp32 -> [128,K] fp16 ----------------
__global__ void prep_bt(const float* __restrict__ W, __half* __restrict__ bt,
                        int K, size_t wStr, size_t oStr)
{
    W  += (size_t)blockIdx.y * wStr;
    bt += (size_t)blockIdx.y * oStr;
    int i = blockIdx.x * 256 + threadIdx.x;
    if (i < 128 * K) {
        int n = i / K, k = i - n * K;
        bt[i] = __float2half_rn(W[(size_t)k * 128 + n]);
    }
}

// ---------------- HGEMM fp16 single-term: C[M,128] = act(A@B + bias) ----------------
// A: fp16 [M,K] (AH=1) or fp32 (AH=0, converted on load). B: fp16 [128,K] K-major.
// C: fp16 (CH=1) or fp32. ACT: 0=none,1=relu,2=tanh. Batched over blockIdx.y.
#define PAD 40   // smem row stride in halves; bank-conflict-free for ldmatrix

template <int ACT, int AH, int CH>
__global__ void __launch_bounds__(256, 2) hgemm(
    const void* __restrict__ Av, const __half* __restrict__ B,
    const float* __restrict__ bias, void* __restrict__ Cv,
    int M, int K, int lda, int ldc,
    size_t aStr, size_t bStr, int biasStr, size_t cStr)
{
    __shared__ __align__(16) __half sA[128 * PAD];
    __shared__ __align__(16) __half sB[128 * PAD];

    const int tid = threadIdx.x, wid = tid >> 5, lane = tid & 31;
    const int wm = wid & 3, wn = wid >> 2;   // warp tile: rows 32*wm, cols 64*wn

    B    += (size_t)blockIdx.y * bStr;
    bias += (size_t)blockIdx.y * biasStr;
    const int m0 = blockIdx.x * 128;

    float acc[2][8][4];
#pragma unroll
    for (int i = 0; i < 2; i++)
#pragma unroll
        for (int j = 0; j < 8; j++)
#pragma unroll
            for (int q = 0; q < 4; q++) acc[i][j][q] = 0.f;

    const int a_m = (lane & 7) + ((lane >> 3) & 1) * 8;
    const int a_k = (lane >> 4) * 8;
    const int bln = lane & 15;
    const int b_n = bln & 7;
    const int b_k = ((bln >> 3) & 1) * 8;

    for (int k0 = 0; k0 < K; k0 += 32) {
        if (AH) {
            const __half* A = (const __half*)Av + (size_t)blockIdx.y * aStr;
            // 128 rows x 32 halves = 512 uint4 jobs
#pragma unroll
            for (int l = 0; l < 2; l++) {
                int f = tid + l * 256;
                int r = f >> 2, ch = (f & 3) * 8;
                uint4 v = make_uint4(0, 0, 0, 0);
                if (m0 + r < M)
                    v = *(const uint4*)(A + (size_t)(m0 + r) * lda + k0 + ch);
                *(uint4*)&sA[r * PAD + ch] = v;
            }
        } else {
            const float* A = (const float*)Av + (size_t)blockIdx.y * aStr;
#pragma unroll
            for (int l = 0; l < 4; l++) {
                int f = tid + l * 256;
                int r = f >> 3, c4 = (f & 7) * 4;
                float4 v = make_float4(0.f, 0.f, 0.f, 0.f);
                if (m0 + r < M)
                    v = *(const float4*)(A + (size_t)(m0 + r) * lda + k0 + c4);
                __half2 p0 = __floats2half2_rn(v.x, v.y);
                __half2 p1 = __floats2half2_rn(v.z, v.w);
                *(uint2*)&sA[r * PAD + c4] =
                    make_uint2(*(uint32_t*)&p0, *(uint32_t*)&p1);
            }
        }
        // B tile [128 x 32] halves
#pragma unroll
        for (int l = 0; l < 2; l++) {
            int f = tid + l * 256;
            int r = f >> 2, ch = (f & 3) * 8;
            *(uint4*)&sB[r * PAD + ch] = *(const uint4*)(B + (size_t)r * K + k0 + ch);
        }
        __syncthreads();

#pragma unroll
        for (int ks = 0; ks < 2; ks++) {
            const int kk = ks * 16;
            uint32_t af[2][4];
#pragma unroll
            for (int mt = 0; mt < 2; mt++) {
                int mrow = wm * 32 + mt * 16 + a_m;
                ldsm_x4(af[mt], smem_u32(&sA[mrow * PAD + kk + a_k]));
            }
#pragma unroll
            for (int nt = 0; nt < 8; nt++) {
                int nrow = wn * 64 + nt * 8 + b_n;
                uint32_t bf[2];
                ldsm_x2(bf, smem_u32(&sB[nrow * PAD + kk + b_k]));
#pragma unroll
                for (int mt = 0; mt < 2; mt++)
                    mma_f16(acc[mt][nt], af[mt], bf);
            }
        }
        __syncthreads();
    }

    // epilogue: frag (r = lane/4, c = 2*(lane%4)); rows r, r+8
    const int fr = lane >> 2, fc = (lane & 3) * 2;
#pragma unroll
    for (int mt = 0; mt < 2; mt++) {
#pragma unroll
        for (int half_ = 0; half_ < 2; half_++) {
            int gr = m0 + wm * 32 + mt * 16 + fr + half_ * 8;
            if (gr >= M) continue;
#pragma unroll
            for (int nt = 0; nt < 8; nt++) {
                int gc = wn * 64 + nt * 8 + fc;
                float vx = acc[mt][nt][half_ * 2 + 0] + bias[gc + 0];
                float vy = acc[mt][nt][half_ * 2 + 1] + bias[gc + 1];
                if (ACT == 1) { vx = fmaxf(vx, 0.f); vy = fmaxf(vy, 0.f); }
                else if (ACT == 2) { vx = tanhf(vx); vy = tanhf(vy); }
                if (CH) {
                    __half* C = (__half*)Cv + (size_t)blockIdx.y * cStr;
                    *(__half2*)(C + (size_t)gr * ldc + gc) = __floats2half2_rn(vx, vy);
                } else {
                    float* C = (float*)Cv + (size_t)blockIdx.y * cStr;
                    *(float2*)(C + (size_t)gr * ldc + gc) = make_float2(vx, vy);
                }
            }
        }
    }
}

// ---------------- gather tss/rs into feat cols [128:256) (fp16) ----------------
__global__ void gather_emb(const float* __restrict__ tss, const float* __restrict__ rs,
                           const int* __restrict__ nid, __half* __restrict__ feat, int n)
{
    int i = blockIdx.x * blockDim.x + threadIdx.x;
    int row = i >> 7, c = i & 127;
    if (row < n) {
        int g = nid[row];
        float v = (c < 64) ? tss[(size_t)g * 64 + c] : rs[(size_t)g * 64 + (c - 64)];
        feat[(size_t)row * 256 + 128 + c] = __float2half_rn(v);
    }
}

// ---------------- CSR build (3 relations batched) ----------------
__global__ void hist_k(const int* __restrict__ dst, int* __restrict__ cnt, int E, int ndst)
{
    int e = blockIdx.x * blockDim.x + threadIdx.x;
    if (e < 3 * E) atomicAdd(&cnt[(e / E) * ndst + dst[e]], 1);
}

__global__ void scan_part(const int* __restrict__ cnt, int* __restrict__ off,
                          int* __restrict__ bsum, int n)
{
    __shared__ int ws[32];
    int tid = threadIdx.x, lane = tid & 31, w = tid >> 5;
    int i = blockIdx.x * 1024 + tid;
    int v = (i < n) ? cnt[i] : 0;
    int x = v;
#pragma unroll
    for (int o = 1; o < 32; o <<= 1) {
        int t = __shfl_up_sync(0xFFFFFFFFu, x, o);
        if (lane >= o) x += t;
    }
    if (lane == 31) ws[w] = x;
    __syncthreads();
    if (w == 0) {
        int y = ws[lane];
#pragma unroll
        for (int o = 1; o < 32; o <<= 1) {
            int t = __shfl_up_sync(0xFFFFFFFFu, y, o);
            if (lane >= o) y += t;
        }
        ws[lane] = y;
    }
    __syncthreads();
    int excl = x - v + (w ? ws[w - 1] : 0);
    if (i < n) off[i] = excl;
    if (tid == 1023) bsum[blockIdx.x] = excl + v;
}

__global__ void scan_bs(int* __restrict__ bsum, int* __restrict__ off, int nb, int n)
{
    __shared__ int sh[64];
    int tid = threadIdx.x;
    int v = (tid < nb) ? bsum[tid] : 0;
    sh[tid] = v;
    __syncthreads();
    for (int d = 1; d < 64; d <<= 1) {
        int t = (tid >= d) ? sh[tid - d] : 0;
        __syncthreads();
        sh[tid] += t;
        __syncthreads();
    }
    if (tid < nb) bsum[tid] = sh[tid] - v;
    if (tid == 0) off[n] = sh[63];
}

__global__ void scan_add(int* __restrict__ off, const int* __restrict__ bsum,
                         int* __restrict__ cur, int n)
{
    int i = blockIdx.x * 1024 + threadIdx.x;
    if (i < n) {
        int o = off[i] + bsum[blockIdx.x];
        off[i] = o;
        cur[i] = o;
    }
}

__global__ void scatter_k(const int* __restrict__ src, const int* __restrict__ dst,
                          int* __restrict__ cur, int* __restrict__ sorted, int E, int ndst)
{
    int e = blockIdx.x * blockDim.x + threadIdx.x;
    if (e < 3 * E) {
        int p = atomicAdd(&cur[(e / E) * ndst + dst[e]], 1);
        sorted[p] = src[e];
    }
}

// ---------------- aggregation (fp16 feats, fp32 math, deterministic) ----------------
__global__ void aggregate_k(const __half* __restrict__ feat, const int* __restrict__ off,
                            const int* __restrict__ sorted, __half* __restrict__ msg)
{
    __shared__ int idx[1024];
    int b = blockIdx.x;
    int s0 = off[b], s1 = off[b + 1];
    int deg = s1 - s0;
    if (deg > 1024) deg = 1024;
    for (int i = threadIdx.x; i < deg; i += blockDim.x) idx[i] = sorted[s0 + i];
    __syncthreads();
    for (int p = 0; p < deg; p++) {
        for (int j = (p & 1) + 2 * threadIdx.x; j + 1 < deg; j += 2 * blockDim.x) {
            int a = idx[j], bb = idx[j + 1];
            if (a > bb) { idx[j] = bb; idx[j + 1] = a; }
        }
        __syncthreads();
    }
    int c = threadIdx.x;
    float sum = 0.f, mx = -INFINITY;
    for (int i = 0; i < deg; i++) {
        float v = __half2float(__ldg(&feat[(size_t)idx[i] * 256 + c]));
        sum += v;
        mx = fmaxf(mx, v);
    }
    float mean = deg ? sum / (float)deg : 0.f;
    if (!deg) mx = 0.f;
    size_t base = (size_t)b * 768;
    msg[base + c]       = __float2half_rn(mx);
    msg[base + 256 + c] = __float2half_rn(mean);
    msg[base + 512 + c] = __float2half_rn(sum);
}

// ---------------- attention ----------------
__global__ void attn_dot(const float* __restrict__ t, const float* __restrict__ w2,
                         float* __restrict__ partial, int totalrows)
{
    __shared__ float sh[8];
    int warp = threadIdx.x >> 5, lane = threadIdx.x & 31;
    int row = blockIdx.x * 8 + warp;
    float s = 0.f;
    if (row < totalrows) {
        const float* tr = &t[(size_t)row * 128];
        for (int i = lane; i < 128; i += 32) s += tr[i] * w2[i];
    }
    for (int o = 16; o; o >>= 1) s += __shfl_xor_sync(0xFFFFFFFFu, s, o);
    if (!lane) sh[warp] = s;
    __syncthreads();
    if (threadIdx.x == 0) {
        float tot = 0.f;
        for (int i = 0; i < 8; i++) tot += sh[i];
        partial[blockIdx.x] = tot;
    }
}

__global__ void attn_fin(const float* __restrict__ partial, int bpr, float invN,
                         float* __restrict__ beta)
{
    __shared__ float sh[256];
    __shared__ float w[3];
    for (int r = 0; r < 3; r++) {
        float s = 0.f;
        for (int i = threadIdx.x; i < bpr; i += 256) s += partial[r * bpr + i];
        sh[threadIdx.x] = s;
        __syncthreads();
        for (int o = 128; o; o >>= 1) {
            if (threadIdx.x < o) sh[threadIdx.x] += sh[threadIdx.x + o];
            __syncthreads();
        }
        if (threadIdx.x == 0) w[r] = sh[0] * invN;
        __syncthreads();
    }
    if (threadIdx.x == 0) {
        float m = fmaxf(w[0], fmaxf(w[1], w[2]));
        float e0 = expf(w[0] - m), e1 = expf(w[1] - m), e2 = expf(w[2] - m);
        float inv = 1.f / (e0 + e1 + e2);
        beta[0] = e0 * inv; beta[1] = e1 * inv; beta[2] = e2 * inv;
    }
}

// combine: z (fp32) weighted by beta -> either fp16 feat (relu) or fp32 out
__global__ void combine_k(const float* __restrict__ z, const float* __restrict__ beta,
                          __half* __restrict__ outh, float* __restrict__ outf,
                          int n, int zstride, int ldc, int do_relu)
{
    int i = blockIdx.x * blockDim.x + threadIdx.x;
    int row = i >> 7, c = i & 127;
    if (row < n) {
        size_t o = (size_t)row * 128 + c;
        float v = beta[0] * z[o] + beta[1] * z[o + (size_t)zstride]
                + beta[2] * z[o + 2 * (size_t)zstride];
        if (do_relu) v = fmaxf(v, 0.f);
        if (outh) outh[(size_t)row * ldc + c] = __float2half_rn(v);
        else      outf[(size_t)row * ldc + c] = v;
    }
}

__global__ void pred_k(const float* __restrict__ h, const float* __restrict__ w,
                       const float* __restrict__ b, float* __restrict__ out, int n)
{
    int gwarp = (blockIdx.x * blockDim.x + threadIdx.x) >> 5;
    int lane = threadIdx.x & 31;
    if (gwarp < n) {
        const float* hr = &h[(size_t)gwarp * 128];
        float s = 0.f;
        for (int i = lane; i < 128; i += 32) s += hr[i] * w[i];
        for (int o = 16; o; o >>= 1) s += __shfl_xor_sync(0xFFFFFFFFu, s, o);
        if (!lane) out[gwarp] = 1.f / (1.f + expf(-(s + b[0])));
    }
}

// ---------------- host orchestration ----------------
static inline int cdiv(int a, int b) { return (a + b - 1) / b; }

extern "C" void kernel_launch(void* const* d_in, const int* in_sizes, int n_in,
                              void* d_out, int out_size)
{
    const float* x_user   = (const float*)d_in[0];
    const float* tss      = (const float*)d_in[1];
    const float* rs       = (const float*)d_in[2];
    const int*   src_nid0 = (const int*)d_in[3];
    const int*   src_nid1 = (const int*)d_in[4];
    const int*   e0_src   = (const int*)d_in[5];
    const int*   e0_dst   = (const int*)d_in[6];
    const int*   e1_src   = (const int*)d_in[7];
    const int*   e1_dst   = (const int*)d_in[8];
    const float* embed_w  = (const float*)d_in[9];
    const float* embed_b  = (const float*)d_in[10];
    const float* attn_w1  = (const float*)d_in[23];
    const float* attn_b1  = (const float*)d_in[24];
    const float* attn_w2  = (const float*)d_in[25];
    const float* pred_w   = (const float*)d_in[26];
    const float* pred_b   = (const float*)d_in[27];
    float* out = (float*)d_out;

    __half *feat0, *feat1, *msg, *inp, *bt;
    float *z, *t, *h2, *partial, *beta;
    int *cnt, *off, *cur, *sorted, *bsum;
    cudaGetSymbolAddress((void**)&feat0, g_feat0);
    cudaGetSymbolAddress((void**)&feat1, g_feat1);
    cudaGetSymbolAddress((void**)&msg, g_msg);
    cudaGetSymbolAddress((void**)&inp, g_inp);
    cudaGetSymbolAddress((void**)&z, g_z);
    cudaGetSymbolAddress((void**)&t, g_t);
    cudaGetSymbolAddress((void**)&h2, g_h2);
    cudaGetSymbolAddress((void**)&partial, g_partial);
    cudaGetSymbolAddress((void**)&beta, g_beta);
    cudaGetSymbolAddress((void**)&cnt, g_cnt);
    cudaGetSymbolAddress((void**)&off, g_off);
    cudaGetSymbolAddress((void**)&cur, g_cur);
    cudaGetSymbolAddress((void**)&sorted, g_sorted);
    cudaGetSymbolAddress((void**)&bsum, g_bsum);
    cudaGetSymbolAddress((void**)&bt, g_bt);

    // --- weight prep: transpose + fp16 ---
    prep_bt<<<dim3(cdiv(128 * 128, 256), 1), 256>>>(embed_w, bt + BT_EMBED, 128, 0, 0);
    prep_bt<<<dim3(cdiv(128 * 128, 256), 1), 256>>>(attn_w1, bt + BT_ATTN, 128, 0, 0);
    for (int layer = 0; layer < 2; layer++) {
        const float* fc1w = (const float*)d_in[11 + layer * 6];
        const float* fc2w = (const float*)d_in[13 + layer * 6];
        const float* fc3w = (const float*)d_in[15 + layer * 6];
        size_t o1 = layer ? BT_L2F1 : BT_L1F1;
        size_t o2 = layer ? BT_L2F2 : BT_L1F2;
        size_t o3 = layer ? BT_L2F3 : BT_L1F3;
        prep_bt<<<dim3(cdiv(128 * 256, 256), 3), 256>>>(fc1w, bt + o1, 256,
                                                        (size_t)256 * 128, (size_t)128 * 256);
        prep_bt<<<dim3(cdiv(128 * 768, 256), 3), 256>>>(fc2w, bt + o2, 768,
                                                        (size_t)768 * 128, (size_t)128 * 768);
        prep_bt<<<dim3(cdiv(128 * 256, 256), 3), 256>>>(fc3w, bt + o3, 256,
                                                        (size_t)256 * 128, (size_t)128 * 256);
    }

    // feat0 = [x_user @ embed_w + b | tss[src_nid0] | rs[src_nid0]]  (fp16)
    hgemm<0, 0, 1><<<dim3(cdiv(N0v, 128), 1), 256>>>(
        x_user, bt + BT_EMBED, embed_b, feat0, N0v, 128, 128, 256, 0, 0, 0, 0);
    gather_emb<<<cdiv(N0v * 128, 256), 256>>>(tss, rs, src_nid0, feat0, N0v);

    for (int layer = 0; layer < 2; layer++) {
        const int E = layer ? E1v : E0v;
        const int ndst = layer ? N2v : N1v;
        const int* esrc = layer ? e1_src : e0_src;
        const int* edst = layer ? e1_dst : e0_dst;
        const __half* srcfeat = layer ? feat1 : feat0;
        const float* fc1b = (const float*)d_in[12 + layer * 6];
        const float* fc2b = (const float*)d_in[14 + layer * 6];
        const float* fc3b = (const float*)d_in[16 + layer * 6];
        size_t o1 = layer ? BT_L2F1 : BT_L1F1;
        size_t o2 = layer ? BT_L2F2 : BT_L1F2;
        size_t o3 = layer ? BT_L2F3 : BT_L1F3;

        // --- batched CSR build + aggregation ---
        int n = 3 * ndst;
        int nb = cdiv(n, 1024);
        cudaMemsetAsync(cnt, 0, n * sizeof(int));
        hist_k<<<cdiv(3 * E, 256), 256>>>(edst, cnt, E, ndst);
        scan_part<<<nb, 1024>>>(cnt, off, bsum, n);
        scan_bs<<<1, 64>>>(bsum, off, nb, n);
        scan_add<<<nb, 1024>>>(off, bsum, cur, n);
        scatter_k<<<cdiv(3 * E, 256), 256>>>(esrc, edst, cur, sorted, E, ndst);
        aggregate_k<<<n, 256>>>(srcfeat, off, sorted, msg);

        // --- per-relation GEMMs (batched over blockIdx.y) ---
        // inp[r][:,0:128] = relu(msg[r] @ fc2w[r] + b2)
        hgemm<1, 1, 1><<<dim3(cdiv(ndst, 128), 3), 256>>>(
            msg, bt + o2, fc2b, inp, ndst, 768, 768, 256,
            (size_t)ndst * 768, (size_t)128 * 768, 128, (size_t)ndst * 256);
        // inp[r][:,128:256] = relu(dstfeat @ fc1w[r] + b1)
        hgemm<1, 1, 1><<<dim3(cdiv(ndst, 128), 3), 256>>>(
            srcfeat, bt + o1, fc1b, inp + 128, ndst, 256, 256, 256,
            0, (size_t)128 * 256, 128, (size_t)ndst * 256);
        // z[r] = inp[r] @ fc3w[r] + b3   (fp32 out)
        hgemm<0, 1, 0><<<dim3(cdiv(ndst, 128), 3), 256>>>(
            inp, bt + o3, fc3b, z, ndst, 256, 256, 128,
            (size_t)ndst * 256, (size_t)128 * 256, 128, (size_t)ndst * 128);

        // --- semantic attention over z [3, ndst, 128] ---
        int rows = 3 * ndst;
        hgemm<2, 0, 0><<<dim3(cdiv(rows, 128), 1), 256>>>(
            z, bt + BT_ATTN, attn_b1, t, rows, 128, 128, 128, 0, 0, 0, 0);
        attn_dot<<<rows / 8, 256>>>(t, attn_w2, partial, rows);
        attn_fin<<<1, 256>>>(partial, ndst / 8, 1.f / (float)ndst, beta);

        if (layer == 0) {
            combine_k<<<cdiv(ndst * 128, 256), 256>>>(z, beta, feat1, (float*)0,
                                                      ndst, ndst * 128, 256, 1);
            gather_emb<<<cdiv(ndst * 128, 256), 256>>>(tss, rs, src_nid1, feat1, ndst);
        } else {
            combine_k<<<cdiv(ndst * 128, 256), 256>>>(z, beta, (__half*)0, h2,
                                                      ndst, ndst * 128, 128, 0);
        }
    }

    pred_k<<<cdiv(N2v * 32, 256), 256>>>(h2, pred_w, pred_b, out, N2v);
}